// round 6
// baseline (speedup 1.0000x reference)
#include <cuda_runtime.h>
#include <cuda_bf16.h>
#include <cstdint>

#define T_DIM 1024
#define F_DIM 128
#define UNROLL 8
#define CHUNK_T 16                     // 2 tiles per bulk-store chunk (8 KB)
#define N_CHUNKS (T_DIM / CHUNK_T)     // 64
#define EPS_F 1e-5f

__device__ __forceinline__ uint32_t smem_u32(const void* p) {
    return (uint32_t)__cvta_generic_to_shared(p);
}

// One block per (b, c) row. 128 threads, thread = f (coalesced loads).
// Loads: dist-1 register ping-pong (8-16 LDGs in flight / warp).
// Stores: staged in smem, flushed as 8KB cp.async.bulk (UBLKCP) bursts —
// large contiguous writebacks, zero STG in the issue stream.
__global__ __launch_bounds__(128, 7)
void cumulative_groupnorm_kernel(const float* __restrict__ x,
                                 const float* __restrict__ weight,
                                 const float* __restrict__ bias,
                                 float* __restrict__ out,
                                 int C)
{
    __shared__ float s_inv[T_DIM];                         // 4 KB LUT
    __shared__ __align__(16) float sbuf[2][CHUNK_T * F_DIM]; // 2 x 8 KB out staging

    const int f  = threadIdx.x;
    const int bc = blockIdx.x;

    #pragma unroll
    for (int i = 0; i < T_DIM / F_DIM; i++) {
        int idx = f + i * F_DIM;
        s_inv[idx] = 1.0f / (float)(idx + 1);
    }
    __syncthreads();

    const int c = bc % C;
    const float w  = weight[c];
    const float bb = bias[c];

    const size_t base = (size_t)bc * T_DIM * F_DIM;
    const float* __restrict__ xp = x + base + f;
    float* __restrict__ op = out + base;           // chunk-granular dst

    float sum = 0.0f, sumsq = 0.0f;
    float vA[UNROLL], vB[UNROLL];

#define LOAD_T(buf, tbase)                                              \
    _Pragma("unroll")                                                   \
    for (int j = 0; j < UNROLL; j++)                                    \
        buf[j] = __ldcg(xp + (size_t)((tbase) + j) * F_DIM);

#define PROC_T(buf, tbase, sdst)                                        \
    _Pragma("unroll")                                                   \
    for (int j = 0; j < UNROLL; j++) {                                  \
        const int  tt  = (tbase) + j;                                   \
        const float val = buf[j];                                       \
        sum   += val;                                                   \
        sumsq  = fmaf(val, val, sumsq);                                 \
        const float inv  = s_inv[tt];                                   \
        const float mean = sum * inv;                                   \
        const float var  = fmaf(-mean, mean, sumsq * inv);              \
        const float r    = rsqrtf(var + EPS_F);                         \
        (sdst)[j * F_DIM + f] = fmaf((val - mean) * r, w, bb);          \
    }

    // Prologue: tile 0 in flight.
    LOAD_T(vA, 0)

    int p = 0;
    #pragma unroll 1
    for (int chunk = 0; chunk < N_CHUNKS; chunk++) {
        const int t0 = chunk * CHUNK_T;

        LOAD_T(vB, t0 + UNROLL)                 // prefetch second tile
        PROC_T(vA, t0, &sbuf[p][0])
        if (chunk < N_CHUNKS - 1) {
            LOAD_T(vA, t0 + CHUNK_T)            // prefetch next chunk's first tile
        }
        PROC_T(vB, t0 + UNROLL, &sbuf[p][UNROLL * F_DIM])

        __syncthreads();                        // all STS for this chunk visible
        if (threadIdx.x == 0) {
            asm volatile("fence.proxy.async.shared::cta;" ::: "memory");
            const uint32_t src = smem_u32(&sbuf[p][0]);
            float* dst = op + (size_t)t0 * F_DIM;
            asm volatile(
                "cp.async.bulk.global.shared::cta.bulk_group [%0], [%1], %2;"
                :: "l"(dst), "r"(src), "n"(CHUNK_T * F_DIM * 4) : "memory");
            asm volatile("cp.async.bulk.commit_group;" ::: "memory");
            // Wait until the PREVIOUS chunk's bulk store finished reading smem,
            // so the other buffer is safe to overwrite.
            asm volatile("cp.async.bulk.wait_group.read 1;" ::: "memory");
        }
        __syncthreads();                        // release other buffer to all warps
        p ^= 1;
    }

    // Drain the final outstanding bulk store before exit.
    if (threadIdx.x == 0)
        asm volatile("cp.async.bulk.wait_group.read 0;" ::: "memory");

#undef LOAD_T
#undef PROC_T
}

extern "C" void kernel_launch(void* const* d_in, const int* in_sizes, int n_in,
                              void* d_out, int out_size)
{
    const float* x      = (const float*)d_in[0];
    const float* weight = (const float*)d_in[1];
    const float* bias   = (const float*)d_in[2];
    float* out          = (float*)d_out;

    const int C    = in_sizes[1];                       // 256
    const int n_bc = in_sizes[0] / (T_DIM * F_DIM);     // B*C = 1024

    cumulative_groupnorm_kernel<<<n_bc, F_DIM>>>(x, weight, bias, out, C);
}

// round 7
// speedup vs baseline: 1.1771x; 1.1771x over previous
#include <cuda_runtime.h>
#include <cuda_bf16.h>

#define T_DIM 1024
#define F_DIM 128
#define F2    (F_DIM / 2)     // 64 float2 per t-row
#define UNROLL 8
#define EPS_F 1e-5f

// One block (64 threads = 2 warps) per (b, c) row; thread owns 2 adjacent
// f-channels (float2 -> LDG.64/STG.64). Dist-1 ping-pong keeps 8-16 loads
// in flight per warp. Half the dynamic instructions per byte vs scalar:
// lower issue power -> higher sustained clock under the replay loop.
__global__ __launch_bounds__(64, 14)
void cumulative_groupnorm_kernel(const float2* __restrict__ x,
                                 const float* __restrict__ weight,
                                 const float* __restrict__ bias,
                                 float2* __restrict__ out,
                                 int C)
{
    __shared__ float s_inv[T_DIM];   // 1/(t+1) LUT (broadcast reads)
    const int tid = threadIdx.x;     // 0..63
    const int bc  = blockIdx.x;

    #pragma unroll
    for (int i = 0; i < T_DIM / 64; i++) {
        int idx = tid + i * 64;
        s_inv[idx] = 1.0f / (float)(idx + 1);
    }
    __syncthreads();

    const int c = bc % C;
    const float w  = weight[c];
    const float bb = bias[c];

    const size_t base = (size_t)bc * T_DIM * F2 + tid;
    const float2* __restrict__ xp = x + base;
    float2* __restrict__ op = out + base;

    float s0 = 0.f, s1 = 0.f;      // running sums (2 channels)
    float q0 = 0.f, q1 = 0.f;      // running sum-of-squares

    float2 vA[UNROLL], vB[UNROLL];

#define LOAD_T(buf, tbase)                                              \
    _Pragma("unroll")                                                   \
    for (int j = 0; j < UNROLL; j++)                                    \
        buf[j] = __ldcs(xp + (size_t)((tbase) + j) * F2);

#define PROC_T(buf, tbase)                                              \
    _Pragma("unroll")                                                   \
    for (int j = 0; j < UNROLL; j++) {                                  \
        const int tt = (tbase) + j;                                     \
        const float2 val = buf[j];                                      \
        s0 += val.x;  s1 += val.y;                                      \
        q0 = fmaf(val.x, val.x, q0);                                    \
        q1 = fmaf(val.y, val.y, q1);                                    \
        const float inv = s_inv[tt];                                    \
        const float m0 = s0 * inv, m1 = s1 * inv;                       \
        const float r0 = rsqrtf(fmaf(-m0, m0, q0 * inv) + EPS_F);       \
        const float r1 = rsqrtf(fmaf(-m1, m1, q1 * inv) + EPS_F);       \
        float2 o;                                                       \
        o.x = fmaf((val.x - m0) * r0, w, bb);                           \
        o.y = fmaf((val.y - m1) * r1, w, bb);                           \
        __stcs(op + (size_t)tt * F2, o);                                \
    }

    // Prologue: tile 0 in flight.
    LOAD_T(vA, 0)

    #pragma unroll 1
    for (int t = 0; t < T_DIM; t += 2 * UNROLL) {
        LOAD_T(vB, t + UNROLL)             // prefetch tile B
        PROC_T(vA, t)                      // process tile A
        if (t + 2 * UNROLL < T_DIM) {
            LOAD_T(vA, t + 2 * UNROLL)     // prefetch next tile A
        }
        PROC_T(vB, t + UNROLL)             // process tile B
    }

#undef LOAD_T
#undef PROC_T
}

extern "C" void kernel_launch(void* const* d_in, const int* in_sizes, int n_in,
                              void* d_out, int out_size)
{
    const float2* x     = (const float2*)d_in[0];
    const float* weight = (const float*)d_in[1];
    const float* bias   = (const float*)d_in[2];
    float2* out         = (float2*)d_out;

    const int C    = in_sizes[1];                       // 256
    const int n_bc = in_sizes[0] / (T_DIM * F_DIM);     // B*C = 1024

    cumulative_groupnorm_kernel<<<n_bc, 64>>>(x, weight, bias, out, C);
}